// round 16
// baseline (speedup 1.0000x reference)
#include <cuda_runtime.h>
#include <cuda_fp16.h>

#define NPB 16
#define THREADS 256

// Fragment-major fp16 weights (packed by pack_w; layout identical to R13/R14):
// g_WtA[(((i*4+q)*2+kc)*4+kt)*32+lane], q: 0=w0x 1=w0y 2=w1y 3=w1x  (8KB per i)
//   -> for each i: [0,4K) = pass A1 (q0,q1), [4K,8K) = pass A2 (q2,q3)
// g_WtB[(((i*2+qq)*2+kc)*4+kt)*32+lane], qq: 0=w2x(W3_1e) 1=w2y(W3_2e) (4KB per i)
//   -> for each i: [0,2K) = pass B1, [2K,4K) = pass B2
__device__ __align__(16) uint2 g_WtA[32768];
__device__ __align__(16) uint2 g_WtB[16384];

__device__ __forceinline__ unsigned h2u(float a, float b) {
    __half2 h = __floats2half2_rn(a, b);
    return *(unsigned*)&h;
}
__device__ __forceinline__ void mma16(float& d0, float& d1, float& d2, float& d3,
                                      unsigned a0, unsigned a1, unsigned a2, unsigned a3,
                                      unsigned b0, unsigned b1) {
    asm volatile("mma.sync.aligned.m16n8k16.row.col.f32.f16.f16.f32 "
                 "{%0,%1,%2,%3}, {%4,%5,%6,%7}, {%8,%9}, {%0,%1,%2,%3};"
                 : "+f"(d0), "+f"(d1), "+f"(d2), "+f"(d3)
                 : "r"(a0), "r"(a1), "r"(a2), "r"(a3), "r"(b0), "r"(b1));
}
__device__ __forceinline__ unsigned s2u(const void* p) {
    return (unsigned)__cvta_generic_to_shared(p);
}
__device__ __forceinline__ void cp16(unsigned dst, const void* src) {
    asm volatile("cp.async.cg.shared.global [%0], [%1], 16;" :: "r"(dst), "l"(src));
}
__device__ __forceinline__ void cp_commit() {
    asm volatile("cp.async.commit_group;" ::: "memory");
}
__device__ __forceinline__ void cp_wait0() {
    asm volatile("cp.async.wait_group 0;" ::: "memory");
}
__device__ __forceinline__ void barall() {
    asm volatile("bar.sync 0, %0;" :: "n"(THREADS) : "memory");
}

__global__ void pack_w(const float* __restrict__ W3_0e, const float* __restrict__ W3_1o,
                       const float* __restrict__ W3_1e, const float* __restrict__ W3_2e)
{
    int t = blockIdx.x * blockDim.x + threadIdx.x;
    if (t >= 49152) return;
    int lane = t & 31;
    int g = lane >> 2, tig = lane & 3;
    if (t < 32768) {
        int r = t >> 5;
        int kt = r & 3;  r >>= 2;
        int kc = r & 1;  r >>= 1;
        int q  = r & 3;
        int i  = r >> 2;
        int j0 = kc * 16 + 2 * tig;
        int n  = kt * 8 + g;
        const float* src; int off = 0;
        switch (q) {
            case 0: src = W3_0e; off = 0;     break;
            case 1: src = W3_0e; off = 32768; break;
            case 2: src = W3_1o; off = 32768; break;
            default: src = W3_1o; off = 0;    break;
        }
        uint2 w;
        w.x = h2u(src[off + (i*32 + j0    )*32 + n], src[off + (i*32 + j0 + 1)*32 + n]);
        w.y = h2u(src[off + (i*32 + j0 + 8)*32 + n], src[off + (i*32 + j0 + 9)*32 + n]);
        g_WtA[t] = w;
    } else {
        int t2 = t - 32768;
        int r = t2 >> 5;
        int kt = r & 3;  r >>= 2;
        int kc = r & 1;  r >>= 1;
        int qq = r & 1;
        int i  = r >> 1;
        int j0 = kc * 16 + 2 * tig;
        int n  = kt * 8 + g;
        const float* src = qq ? W3_2e : W3_1e;
        uint2 w;
        w.x = h2u(src[(i*32 + j0    )*32 + n], src[(i*32 + j0 + 1)*32 + n]);
        w.y = h2u(src[(i*32 + j0 + 8)*32 + n], src[(i*32 + j0 + 9)*32 + n]);
        g_WtB[t2] = w;
    }
}

// SMEM (40KB):
//   [0,16K)   prologue Wsh (W1_0,W1_1,W2_0,W2_1) -> after prologue:
//             wbufA [0,8K) = 2 x 4KB dbuf, wbufB [8K,12K) = 2 x 2KB dbuf
//   [16K,24K) xs (prologue only)
//   [24K,32K) Ash float4[512]
//   [32K,40K) Bsh float4[512]

// A-slab LDB: stream QQ in {0,1} within the staged 4KB slab
#define LDBA(QQ) { \
    B0 = wb[(QQ) * 256 + kt * 32 + lane]; \
    B1 = wb[(QQ) * 256 + 128 + kt * 32 + lane]; }
// B-slab LDB: single stream in the staged 2KB slab
#define LDBB() { \
    B0 = wb[kt * 32 + lane]; \
    B1 = wb[128 + kt * 32 + lane]; }

#define MMA2(AF, P) { \
    dd[P][0]=dd[P][1]=dd[P][2]=dd[P][3]=0.f; \
    mma16(dd[P][0],dd[P][1],dd[P][2],dd[P][3], AF[0][0],AF[0][1],AF[0][2],AF[0][3], B0.x, B0.y); \
    mma16(dd[P][0],dd[P][1],dd[P][2],dd[P][3], AF[1][0],AF[1][1],AF[1][2],AF[1][3], B1.x, B1.y); }

#define FOLDP(P, CH, CL, CH_) { \
    acc[CH][0] += (CL)*dd[P][0]; acc[CH][1] += (CL)*dd[P][1]; \
    acc[CH][2] += (CH_)*dd[P][2]; acc[CH][3] += (CH_)*dd[P][3]; }

__global__ __launch_bounds__(THREADS, 3)
void td_mma(const float* __restrict__ x,
            const float* __restrict__ W1_0, const float* __restrict__ W1_1,
            const float* __restrict__ W2_0, const float* __restrict__ W2_1,
            float* __restrict__ out, int N)
{
    extern __shared__ float smem[];
    float4* Ash = (float4*)((char*)smem + 24576);   // [512]
    float4* Bsh = (float4*)((char*)smem + 32768);   // [512]
    float*  Wsh = smem;                             // prologue [0,16K)
    float*  xs  = smem + 4096;                      // prologue [16K,24K)

    const int tid = threadIdx.x;
    const int n0  = blockIdx.x * NPB;
    const unsigned sB0 = s2u(smem);
    const unsigned sWB = sB0 + 8192;

    // ---- async-stage W1_0,W1_1,W2_0,W2_1 into Wsh ----
    cp16(sB0 +     0 + tid * 16, W1_0 + tid * 4);
    cp16(sB0 +  4096 + tid * 16, W1_1 + tid * 4);
    cp16(sB0 +  8192 + tid * 16, W2_0 + tid * 4);
    cp16(sB0 + 12288 + tid * 16, W2_1 + tid * 4);
    cp_commit();

    // ---- stage x rows ----
    for (int e = tid; e < NPB * 128; e += THREADS) {
        int node = e >> 7;
        xs[e] = (n0 + node < N) ? x[(size_t)(n0 + node) * 128 + (e & 127)] : 0.0f;
    }
    cp_wait0();
    __syncthreads();

    // ---- prologue matvec: A=(s@W1_0, v@W1_1), B=(s@W2_0, v@W2_1) ----
    for (int t = tid; t < NPB * 32 * 2; t += THREADS) {
        int which = (t >= NPB * 32);
        int tt = t & (NPB * 32 - 1);
        int node = tt >> 5, i = tt & 31;
        const float* Ws = Wsh + which * 2048;
        const float* Wv = Ws + 1024;
        const float* xr = xs + node * 128;
        float s = 0.f, v0 = 0.f, v1 = 0.f, v2 = 0.f;
        #pragma unroll
        for (int m = 0; m < 32; ++m) {
            float ws = Ws[m * 32 + i];
            float wv = Wv[m * 32 + i];
            s  += xr[m] * ws;
            v0 += xr[32 + 3 * m + 0] * wv;
            v1 += xr[32 + 3 * m + 1] * wv;
            v2 += xr[32 + 3 * m + 2] * wv;
        }
        float4 r = make_float4(s, v0, v1, v2);
        if (which) Bsh[node * 32 + i] = r;
        else       Ash[node * 32 + i] = r;
    }
    __syncthreads();   // overlays dead

    const int lane = tid & 31, wid = tid >> 5;
    const int kt = wid & 3;
    const int g = lane >> 2, tig = lane & 3;
    const int kbase = kt * 8 + 2 * tig;

    const float C0  = -0.57735026918962576f;
    const float C1  = -0.70710678118654752f;
    const float C2  =  0.70710678118654752f;
    const float C2z =  0.40824829046386302f;

    float dd[2][4];
    uint2 B0, B1;

    if (wid < 4) {
        // ===== A-half: passes A1 (w0x,w0y) and A2 (w1y,w1x) =====
        const int htid = tid;   // 0..127
        unsigned af[4][2][4];
        #pragma unroll
        for (int kc = 0; kc < 2; ++kc) {
            int jb = kc * 16 + 2 * tig;
            float4 P0 = Bsh[g * 32 + jb],           P1 = Bsh[g * 32 + jb + 1];
            float4 Q0 = Bsh[(g + 8) * 32 + jb],     Q1 = Bsh[(g + 8) * 32 + jb + 1];
            float4 R0 = Bsh[g * 32 + jb + 8],       R1 = Bsh[g * 32 + jb + 9];
            float4 S0 = Bsh[(g + 8) * 32 + jb + 8], S1 = Bsh[(g + 8) * 32 + jb + 9];
            af[0][kc][0]=h2u(P0.x,P1.x); af[0][kc][1]=h2u(Q0.x,Q1.x); af[0][kc][2]=h2u(R0.x,R1.x); af[0][kc][3]=h2u(S0.x,S1.x);
            af[1][kc][0]=h2u(P0.y,P1.y); af[1][kc][1]=h2u(Q0.y,Q1.y); af[1][kc][2]=h2u(R0.y,R1.y); af[1][kc][3]=h2u(S0.y,S1.y);
            af[2][kc][0]=h2u(P0.z,P1.z); af[2][kc][1]=h2u(Q0.z,Q1.z); af[2][kc][2]=h2u(R0.z,R1.z); af[2][kc][3]=h2u(S0.z,S1.z);
            af[3][kc][0]=h2u(P0.w,P1.w); af[3][kc][1]=h2u(Q0.w,Q1.w); af[3][kc][2]=h2u(R0.w,R1.w); af[3][kc][3]=h2u(S0.w,S1.w);
        }

        #pragma unroll
        for (int p = 0; p < 2; ++p) {
            barall();   // all threads done with previous pass's buffers
            const char* srcbase = (const char*)g_WtA + p * 4096;
            cp16(sB0 + htid * 16, srcbase + htid * 16);
            cp16(sB0 + 2048 + htid * 16, srcbase + 2048 + htid * 16);
            cp_commit();

            float acc[3][4];
            #pragma unroll
            for (int c = 0; c < 3; ++c) { acc[c][0]=acc[c][1]=acc[c][2]=acc[c][3]=0.f; }

            for (int i = 0; i < 32; ++i) {
                cp_wait0();
                barall();
                if (i + 1 < 32) {
                    const char* s2 = srcbase + (i + 1) * 8192;
                    unsigned dst = sB0 + ((i + 1) & 1) * 4096;
                    cp16(dst + htid * 16, s2 + htid * 16);
                    cp16(dst + 2048 + htid * 16, s2 + 2048 + htid * 16);
                }
                cp_commit();

                const uint2* wb = (const uint2*)((const char*)smem + (i & 1) * 4096);
                float4 AL = Ash[g * 32 + i];
                float4 AH = Ash[(g + 8) * 32 + i];

                if (p == 0) {
                    LDBA(0); MMA2(af[0], 0);           // m0
                    LDBA(1); MMA2(af[1], 1);           // m1
                    FOLDP(0, 0, AL.x, AH.x);           // fold m0
                    MMA2(af[2], 0);                    // m2
                    FOLDP(1, 1, AL.y, AH.y);           // fold m1
                    MMA2(af[3], 1);                    // m3
                    FOLDP(0, 1, AL.z, AH.z);           // fold m2
                    FOLDP(1, 1, AL.w, AH.w);           // fold m3
                } else {
                    LDBA(0); MMA2(af[0], 0);           // m7
                    LDBA(1); MMA2(af[1], 1);           // m4
                    FOLDP(0, 0, AL.y, AH.y);           // fold m7 -> 3 channels
                    FOLDP(0, 1, AL.z, AH.z);
                    FOLDP(0, 2, AL.w, AH.w);
                    MMA2(af[2], 0);                    // m5
                    FOLDP(1, 0, AL.x, AH.x);           // fold m4
                    MMA2(af[3], 1);                    // m6
                    FOLDP(0, 1, AL.x, AH.x);           // fold m5
                    FOLDP(1, 2, AL.x, AH.x);           // fold m6
                }
            }

            // epilogue
            #pragma unroll
            for (int eh = 0; eh < 2; ++eh) {
                int node = n0 + (eh ? g + 8 : g);
                if (node >= N) continue;
                float* o = out + (size_t)node * 384;
                #pragma unroll
                for (int ec = 0; ec < 2; ++ec) {
                    int e = eh * 2 + ec, c = kbase + ec;
                    if (p == 0) {
                        o[c] = acc[0][e] + C0 * acc[1][e];
                    } else {
                        o[32 + 3 * c + 0] = acc[0][e];
                        o[32 + 3 * c + 1] = acc[1][e];
                        o[32 + 3 * c + 2] = acc[2][e];
                    }
                }
            }
        }
    } else {
        // ===== B-half: passes B1 (w2x) and B2 (w2y) =====
        const int htid = tid - 128;   // 0..127
        unsigned af[3][2][4];
        #pragma unroll
        for (int kc = 0; kc < 2; ++kc) {
            int jb = kc * 16 + 2 * tig;
            float4 P0 = Bsh[g * 32 + jb],           P1 = Bsh[g * 32 + jb + 1];
            float4 Q0 = Bsh[(g + 8) * 32 + jb],     Q1 = Bsh[(g + 8) * 32 + jb + 1];
            float4 R0 = Bsh[g * 32 + jb + 8],       R1 = Bsh[g * 32 + jb + 9];
            float4 S0 = Bsh[(g + 8) * 32 + jb + 8], S1 = Bsh[(g + 8) * 32 + jb + 9];
            af[0][kc][0]=h2u(P0.y,P1.y); af[0][kc][1]=h2u(Q0.y,Q1.y); af[0][kc][2]=h2u(R0.y,R1.y); af[0][kc][3]=h2u(S0.y,S1.y);
            af[1][kc][0]=h2u(P0.z,P1.z); af[1][kc][1]=h2u(Q0.z,Q1.z); af[1][kc][2]=h2u(R0.z,R1.z); af[1][kc][3]=h2u(S0.z,S1.z);
            af[2][kc][0]=h2u(P0.w,P1.w); af[2][kc][1]=h2u(Q0.w,Q1.w); af[2][kc][2]=h2u(R0.w,R1.w); af[2][kc][3]=h2u(S0.w,S1.w);
        }

        #pragma unroll
        for (int p = 0; p < 2; ++p) {
            barall();
            const char* srcbase = (const char*)g_WtB + p * 2048;
            cp16(sWB + htid * 16, srcbase + htid * 16);
            cp_commit();

            float acc[5][4];
            #pragma unroll
            for (int c = 0; c < 5; ++c) { acc[c][0]=acc[c][1]=acc[c][2]=acc[c][3]=0.f; }

            for (int i = 0; i < 32; ++i) {
                cp_wait0();
                barall();
                if (i + 1 < 32) {
                    cp16(sWB + ((i + 1) & 1) * 2048 + htid * 16,
                         srcbase + (i + 1) * 4096 + htid * 16);
                }
                cp_commit();

                const uint2* wb = (const uint2*)((const char*)smem + 8192 + (i & 1) * 2048);
                float4 AL = Ash[g * 32 + i];
                float4 AH = Ash[(g + 8) * 32 + i];

                if (p == 0) {
                    LDBB(); MMA2(af[0], 0);            // m8
                    MMA2(af[1], 1);                    // m9
                    FOLDP(0, 1,  AL.w,  AH.w);         // fold m8
                    FOLDP(0, 2, -AL.z, -AH.z);
                    MMA2(af[2], 0);                    // m10
                    FOLDP(1, 2,  AL.y,  AH.y);         // fold m9
                    FOLDP(1, 0, -AL.w, -AH.w);
                    FOLDP(0, 0,  AL.z,  AH.z);         // fold m10
                    FOLDP(0, 1, -AL.y, -AH.y);
                } else {
                    LDBB(); MMA2(af[0], 0);            // m11
                    MMA2(af[1], 1);                    // m12
                    FOLDP(0, 0,  AL.w,  AH.w);         // fold m11
                    FOLDP(0, 1,  AL.z,  AH.z);
                    FOLDP(0, 2, -AL.y, -AH.y);
                    FOLDP(0, 4, -AL.y, -AH.y);
                    MMA2(af[2], 0);                    // m13
                    FOLDP(1, 1,  AL.y,  AH.y);         // fold m12
                    FOLDP(1, 2, 2.f*AL.z, 2.f*AH.z);
                    FOLDP(1, 3,  AL.w,  AH.w);
                    FOLDP(0, 0,  AL.y,  AH.y);         // fold m13
                    FOLDP(0, 2, -AL.w, -AH.w);
                    FOLDP(0, 3,  AL.z,  AH.z);
                    FOLDP(0, 4,  AL.w,  AH.w);
                }
            }

            // epilogue
            #pragma unroll
            for (int eh = 0; eh < 2; ++eh) {
                int node = n0 + (eh ? g + 8 : g);
                if (node >= N) continue;
                float* o = out + (size_t)node * 384;
                #pragma unroll
                for (int ec = 0; ec < 2; ++ec) {
                    int e = eh * 2 + ec, c = kbase + ec;
                    if (p == 0) {
                        o[128 + 3 * c + 0] = C1 * acc[0][e];
                        o[128 + 3 * c + 1] = C1 * acc[1][e];
                        o[128 + 3 * c + 2] = C1 * acc[2][e];
                    } else {
                        o[224 + 5 * c + 0] = C2  * acc[0][e];
                        o[224 + 5 * c + 1] = C2  * acc[1][e];
                        o[224 + 5 * c + 2] = C2z * acc[2][e];
                        o[224 + 5 * c + 3] = C2  * acc[3][e];
                        o[224 + 5 * c + 4] = C2  * acc[4][e];
                    }
                }
            }
        }
    }
}

extern "C" void kernel_launch(void* const* d_in, const int* in_sizes, int n_in,
                              void* d_out, int out_size)
{
    const float* x     = (const float*)d_in[0];
    const float* W1_0  = (const float*)d_in[1];
    const float* W1_1  = (const float*)d_in[2];
    const float* W2_0  = (const float*)d_in[3];
    const float* W2_1  = (const float*)d_in[4];
    const float* W3_0e = (const float*)d_in[5];
    const float* W3_1o = (const float*)d_in[6];
    const float* W3_1e = (const float*)d_in[7];
    const float* W3_2e = (const float*)d_in[8];

    int N = in_sizes[0] / 128;
    int blocks = (N + NPB - 1) / NPB;
    size_t smem = 40960;   // 40KB

    cudaFuncSetAttribute(td_mma, cudaFuncAttributeMaxDynamicSharedMemorySize,
                         (int)smem);

    pack_w<<<192, 256>>>(W3_0e, W3_1o, W3_1e, W3_2e);
    td_mma<<<blocks, THREADS, smem>>>(x, W1_0, W1_1, W2_0, W2_1,
                                      (float*)d_out, N);
}

// round 17
// speedup vs baseline: 1.2164x; 1.2164x over previous
#include <cuda_runtime.h>
#include <cuda_fp16.h>

#define NPB 32
#define THREADS 256

// Direct-LDG weight fragments (uint4 per lane per (i,kt,q)):
//   g_WA[((i*4+kt)*4+q)*32+lane], q: 0=w0x 1=w0y 2=w1y 3=w1x   (256KB)
//   g_WB[((i*4+kt)*2+q)*32+lane], q: 0=w2x(W3_1e) 1=w2y(W3_2e) (128KB)
// uint4 = { b0(kc0), b1(kc0), b0(kc1), b1(kc1) } as __half2 bit patterns.
__device__ __align__(16) uint4 g_WA[16384];
__device__ __align__(16) uint4 g_WB[8192];

__device__ __forceinline__ unsigned h2u(float a, float b) {
    __half2 h = __floats2half2_rn(a, b);
    return *(unsigned*)&h;
}
__device__ __forceinline__ void mma16(float& d0, float& d1, float& d2, float& d3,
                                      unsigned a0, unsigned a1, unsigned a2, unsigned a3,
                                      unsigned b0, unsigned b1) {
    asm volatile("mma.sync.aligned.m16n8k16.row.col.f32.f16.f16.f32 "
                 "{%0,%1,%2,%3}, {%4,%5,%6,%7}, {%8,%9}, {%0,%1,%2,%3};"
                 : "+f"(d0), "+f"(d1), "+f"(d2), "+f"(d3)
                 : "r"(a0), "r"(a1), "r"(a2), "r"(a3), "r"(b0), "r"(b1));
}
__device__ __forceinline__ unsigned s2u(const void* p) {
    return (unsigned)__cvta_generic_to_shared(p);
}
__device__ __forceinline__ void cp16(unsigned dst, const void* src) {
    asm volatile("cp.async.cg.shared.global [%0], [%1], 16;" :: "r"(dst), "l"(src));
}
__device__ __forceinline__ void cp_commit() {
    asm volatile("cp.async.commit_group;" ::: "memory");
}
__device__ __forceinline__ void cp_wait0() {
    asm volatile("cp.async.wait_group 0;" ::: "memory");
}

__global__ void pack_w(const float* __restrict__ W3_0e, const float* __restrict__ W3_1o,
                       const float* __restrict__ W3_1e, const float* __restrict__ W3_2e)
{
    int t = blockIdx.x * blockDim.x + threadIdx.x;
    if (t >= 24576) return;
    int lane = t & 31;
    int g = lane >> 2, tig = lane & 3;
    const float* src; int off = 0; uint4* dst; int idx;
    int kt, q, i;
    if (t < 16384) {
        int r = t >> 5;
        q = r & 3;  r >>= 2;
        kt = r & 3; i = r >> 2;
        switch (q) {
            case 0: src = W3_0e; off = 0;     break;
            case 1: src = W3_0e; off = 32768; break;
            case 2: src = W3_1o; off = 32768; break;
            default: src = W3_1o; off = 0;    break;
        }
        dst = g_WA; idx = t;
    } else {
        int r = (t - 16384) >> 5;
        q = r & 1;  r >>= 1;
        kt = r & 3; i = r >> 2;
        src = q ? W3_2e : W3_1e; off = 0;
        dst = g_WB; idx = t - 16384;
    }
    int n = kt * 8 + g;
    int j = i * 32 + 2 * tig;
    uint4 w;
    w.x = h2u(src[off + (j     ) * 32 + n], src[off + (j + 1 ) * 32 + n]);
    w.y = h2u(src[off + (j + 8 ) * 32 + n], src[off + (j + 9 ) * 32 + n]);
    w.z = h2u(src[off + (j + 16) * 32 + n], src[off + (j + 17) * 32 + n]);
    w.w = h2u(src[off + (j + 24) * 32 + n], src[off + (j + 25) * 32 + n]);
    dst[idx] = w;
}

// SMEM (64KB): prologue: xs [0,16K), Wsh [16K,32K). Persistent: Ash [32K,48K),
// Bsh [48K,64K). No weight buffers — main loop is barrier-free.

#define MMA2R(AF, P, W) { \
    dd[P][0]=dd[P][1]=dd[P][2]=dd[P][3]=0.f; \
    mma16(dd[P][0],dd[P][1],dd[P][2],dd[P][3], AF[0][0],AF[0][1],AF[0][2],AF[0][3], (W).x, (W).y); \
    mma16(dd[P][0],dd[P][1],dd[P][2],dd[P][3], AF[1][0],AF[1][1],AF[1][2],AF[1][3], (W).z, (W).w); }

#define FOLDP(P, CH, CL, CH_) { \
    acc[CH][0] += (CL)*dd[P][0]; acc[CH][1] += (CL)*dd[P][1]; \
    acc[CH][2] += (CH_)*dd[P][2]; acc[CH][3] += (CH_)*dd[P][3]; }

__global__ __launch_bounds__(THREADS, 2)
void td_mma(const float* __restrict__ x,
            const float* __restrict__ W1_0, const float* __restrict__ W1_1,
            const float* __restrict__ W2_0, const float* __restrict__ W2_1,
            float* __restrict__ out, int N)
{
    extern __shared__ float smem[];
    float4* Ash = (float4*)((char*)smem + 32768);   // [1024]
    float4* Bsh = (float4*)((char*)smem + 49152);   // [1024]
    float*  xs  = smem;                             // overlay [0..4096)
    float*  Wsh = smem + 4096;                      // overlay [4096..8192)

    const int tid = threadIdx.x;
    const int n0  = blockIdx.x * NPB;
    const unsigned sW = s2u(smem);

    // ---- async-stage W1_0,W1_1,W2_0,W2_1 into Wsh ----
    cp16(sW + 16384 + tid * 16, W1_0 + tid * 4);
    cp16(sW + 20480 + tid * 16, W1_1 + tid * 4);
    cp16(sW + 24576 + tid * 16, W2_0 + tid * 4);
    cp16(sW + 28672 + tid * 16, W2_1 + tid * 4);
    cp_commit();

    // ---- stage x rows ----
    for (int e = tid; e < NPB * 128; e += THREADS) {
        int node = e >> 7;
        xs[e] = (n0 + node < N) ? x[(size_t)(n0 + node) * 128 + (e & 127)] : 0.0f;
    }
    cp_wait0();
    __syncthreads();

    // ---- prologue matvec: A=(s@W1_0, v@W1_1), B=(s@W2_0, v@W2_1) ----
    for (int t = tid; t < NPB * 32 * 2; t += THREADS) {
        int which = (t >= NPB * 32);
        int tt = t & (NPB * 32 - 1);
        int node = tt >> 5, i = tt & 31;
        const float* Ws = Wsh + which * 2048;
        const float* Wv = Ws + 1024;
        const float* xr = xs + node * 128;
        float s = 0.f, v0 = 0.f, v1 = 0.f, v2 = 0.f;
        #pragma unroll
        for (int m = 0; m < 32; ++m) {
            float ws = Ws[m * 32 + i];
            float wv = Wv[m * 32 + i];
            s  += xr[m] * ws;
            v0 += xr[32 + 3 * m + 0] * wv;
            v1 += xr[32 + 3 * m + 1] * wv;
            v2 += xr[32 + 3 * m + 2] * wv;
        }
        float4 r = make_float4(s, v0, v1, v2);
        if (which) Bsh[node * 32 + i] = r;
        else       Ash[node * 32 + i] = r;
    }
    __syncthreads();   // Ash/Bsh live; last barrier in the kernel

    const int lane = tid & 31, wid = tid >> 5;
    const int tile = wid & 1, kt = wid >> 1;
    const int g = lane >> 2, tig = lane & 3;
    const int tb = tile * 16;
    const int kbase = kt * 8 + 2 * tig;

    const float C0  = -0.57735026918962576f;
    const float C1  = -0.70710678118654752f;
    const float C2  =  0.70710678118654752f;
    const float C2z =  0.40824829046386302f;

    float dd[2][4];

    // ================= PASS A: q=0..3 -> channels 0..4 =====================
    {
        unsigned af[4][2][4];
        #pragma unroll
        for (int kc = 0; kc < 2; ++kc) {
            int jb = kc * 16 + 2 * tig;
            float4 P0 = Bsh[(tb + g) * 32 + jb],         P1 = Bsh[(tb + g) * 32 + jb + 1];
            float4 Q0 = Bsh[(tb + g + 8) * 32 + jb],     Q1 = Bsh[(tb + g + 8) * 32 + jb + 1];
            float4 R0 = Bsh[(tb + g) * 32 + jb + 8],     R1 = Bsh[(tb + g) * 32 + jb + 9];
            float4 S0 = Bsh[(tb + g + 8) * 32 + jb + 8], S1 = Bsh[(tb + g + 8) * 32 + jb + 9];
            af[0][kc][0]=h2u(P0.x,P1.x); af[0][kc][1]=h2u(Q0.x,Q1.x); af[0][kc][2]=h2u(R0.x,R1.x); af[0][kc][3]=h2u(S0.x,S1.x);
            af[1][kc][0]=h2u(P0.y,P1.y); af[1][kc][1]=h2u(Q0.y,Q1.y); af[1][kc][2]=h2u(R0.y,R1.y); af[1][kc][3]=h2u(S0.y,S1.y);
            af[2][kc][0]=h2u(P0.z,P1.z); af[2][kc][1]=h2u(Q0.z,Q1.z); af[2][kc][2]=h2u(R0.z,R1.z); af[2][kc][3]=h2u(S0.z,S1.z);
            af[3][kc][0]=h2u(P0.w,P1.w); af[3][kc][1]=h2u(Q0.w,Q1.w); af[3][kc][2]=h2u(R0.w,R1.w); af[3][kc][3]=h2u(S0.w,S1.w);
        }
        float acc[5][4];
        #pragma unroll
        for (int c = 0; c < 5; ++c) { acc[c][0]=acc[c][1]=acc[c][2]=acc[c][3]=0.f; }

        const uint4* Wp = g_WA + kt * 128 + lane;   // (i*4+kt)*4*32
        uint4 wA0 = Wp[0], wA1 = Wp[32], wA2 = Wp[64], wA3 = Wp[96];

        for (int i = 0; i < 32; ++i) {
            uint4 wN0, wN1, wN2, wN3;
            if (i + 1 < 32) {
                const uint4* Wn = Wp + (i + 1) * 512;
                wN0 = Wn[0]; wN1 = Wn[32]; wN2 = Wn[64]; wN3 = Wn[96];
            }
            float4 AL = Ash[(tb + g) * 32 + i];
            float4 AH = Ash[(tb + g + 8) * 32 + i];

            MMA2R(af[0], 0, wA0);                     // m0
            MMA2R(af[1], 1, wA1);                     // m1
            FOLDP(0, 0, AL.x, AH.x);                  // fold m0
            MMA2R(af[2], 0, wA1);                     // m2
            FOLDP(1, 1, AL.y, AH.y);                  // fold m1
            MMA2R(af[3], 1, wA1);                     // m3
            FOLDP(0, 1, AL.z, AH.z);                  // fold m2
            MMA2R(af[0], 0, wA2);                     // m7
            FOLDP(1, 1, AL.w, AH.w);                  // fold m3
            MMA2R(af[1], 1, wA3);                     // m4
            FOLDP(0, 2, AL.y, AH.y);                  // fold m7 -> 3 channels
            FOLDP(0, 3, AL.z, AH.z);
            FOLDP(0, 4, AL.w, AH.w);
            MMA2R(af[2], 0, wA3);                     // m5
            FOLDP(1, 2, AL.x, AH.x);                  // fold m4
            MMA2R(af[3], 1, wA3);                     // m6
            FOLDP(0, 3, AL.x, AH.x);                  // fold m5
            FOLDP(1, 4, AL.x, AH.x);                  // fold m6

            wA0 = wN0; wA1 = wN1; wA2 = wN2; wA3 = wN3;
        }

        #pragma unroll
        for (int eh = 0; eh < 2; ++eh) {
            int node = n0 + tb + (eh ? g + 8 : g);
            if (node >= N) continue;
            float* o = out + (size_t)node * 384;
            #pragma unroll
            for (int ec = 0; ec < 2; ++ec) {
                int e = eh * 2 + ec, c = kbase + ec;
                o[c] = acc[0][e] + C0 * acc[1][e];
                o[32 + 3 * c + 0] = acc[2][e];
                o[32 + 3 * c + 1] = acc[3][e];
                o[32 + 3 * c + 2] = acc[4][e];
            }
        }
    }

    // ================= PASS B: q=0..1 (w2x,w2y) -> channels 5..12 ==========
    {
        unsigned af[3][2][4];
        #pragma unroll
        for (int kc = 0; kc < 2; ++kc) {
            int jb = kc * 16 + 2 * tig;
            float4 P0 = Bsh[(tb + g) * 32 + jb],         P1 = Bsh[(tb + g) * 32 + jb + 1];
            float4 Q0 = Bsh[(tb + g + 8) * 32 + jb],     Q1 = Bsh[(tb + g + 8) * 32 + jb + 1];
            float4 R0 = Bsh[(tb + g) * 32 + jb + 8],     R1 = Bsh[(tb + g) * 32 + jb + 9];
            float4 S0 = Bsh[(tb + g + 8) * 32 + jb + 8], S1 = Bsh[(tb + g + 8) * 32 + jb + 9];
            af[0][kc][0]=h2u(P0.y,P1.y); af[0][kc][1]=h2u(Q0.y,Q1.y); af[0][kc][2]=h2u(R0.y,R1.y); af[0][kc][3]=h2u(S0.y,S1.y);
            af[1][kc][0]=h2u(P0.z,P1.z); af[1][kc][1]=h2u(Q0.z,Q1.z); af[1][kc][2]=h2u(R0.z,R1.z); af[1][kc][3]=h2u(S0.z,S1.z);
            af[2][kc][0]=h2u(P0.w,P1.w); af[2][kc][1]=h2u(Q0.w,Q1.w); af[2][kc][2]=h2u(R0.w,R1.w); af[2][kc][3]=h2u(S0.w,S1.w);
        }
        float acc[8][4];
        #pragma unroll
        for (int c = 0; c < 8; ++c) { acc[c][0]=acc[c][1]=acc[c][2]=acc[c][3]=0.f; }

        const uint4* Wp = g_WB + kt * 64 + lane;    // (i*4+kt)*2*32
        uint4 wB0 = Wp[0], wB1 = Wp[32];

        for (int i = 0; i < 32; ++i) {
            uint4 wN0, wN1;
            if (i + 1 < 32) {
                const uint4* Wn = Wp + (i + 1) * 256;
                wN0 = Wn[0]; wN1 = Wn[32];
            }
            float4 AL = Ash[(tb + g) * 32 + i];
            float4 AH = Ash[(tb + g + 8) * 32 + i];

            MMA2R(af[0], 0, wB0);                     // m8
            MMA2R(af[1], 1, wB0);                     // m9
            FOLDP(0, 1,  AL.w,  AH.w);                // fold m8
            FOLDP(0, 2, -AL.z, -AH.z);
            MMA2R(af[2], 0, wB0);                     // m10
            FOLDP(1, 2,  AL.y,  AH.y);                // fold m9
            FOLDP(1, 0, -AL.w, -AH.w);
            MMA2R(af[0], 1, wB1);                     // m11
            FOLDP(0, 0,  AL.z,  AH.z);                // fold m10
            FOLDP(0, 1, -AL.y, -AH.y);
            MMA2R(af[1], 0, wB1);                     // m12
            FOLDP(1, 3,  AL.w,  AH.w);                // fold m11
            FOLDP(1, 4,  AL.z,  AH.z);
            FOLDP(1, 5, -AL.y, -AH.y);
            FOLDP(1, 7, -AL.y, -AH.y);
            MMA2R(af[2], 1, wB1);                     // m13
            FOLDP(0, 4,  AL.y,  AH.y);                // fold m12
            FOLDP(0, 5, 2.f*AL.z, 2.f*AH.z);
            FOLDP(0, 6,  AL.w,  AH.w);
            FOLDP(1, 3,  AL.y,  AH.y);                // fold m13
            FOLDP(1, 5, -AL.w, -AH.w);
            FOLDP(1, 6,  AL.z,  AH.z);
            FOLDP(1, 7,  AL.w,  AH.w);

            wB0 = wN0; wB1 = wN1;
        }

        #pragma unroll
        for (int eh = 0; eh < 2; ++eh) {
            int node = n0 + tb + (eh ? g + 8 : g);
            if (node >= N) continue;
            float* o = out + (size_t)node * 384;
            #pragma unroll
            for (int ec = 0; ec < 2; ++ec) {
                int e = eh * 2 + ec, c = kbase + ec;
                o[128 + 3 * c + 0] = C1 * acc[0][e];
                o[128 + 3 * c + 1] = C1 * acc[1][e];
                o[128 + 3 * c + 2] = C1 * acc[2][e];
                o[224 + 5 * c + 0] = C2  * acc[3][e];
                o[224 + 5 * c + 1] = C2  * acc[4][e];
                o[224 + 5 * c + 2] = C2z * acc[5][e];
                o[224 + 5 * c + 3] = C2  * acc[6][e];
                o[224 + 5 * c + 4] = C2  * acc[7][e];
            }
        }
    }
}

extern "C" void kernel_launch(void* const* d_in, const int* in_sizes, int n_in,
                              void* d_out, int out_size)
{
    const float* x     = (const float*)d_in[0];
    const float* W1_0  = (const float*)d_in[1];
    const float* W1_1  = (const float*)d_in[2];
    const float* W2_0  = (const float*)d_in[3];
    const float* W2_1  = (const float*)d_in[4];
    const float* W3_0e = (const float*)d_in[5];
    const float* W3_1o = (const float*)d_in[6];
    const float* W3_1e = (const float*)d_in[7];
    const float* W3_2e = (const float*)d_in[8];

    int N = in_sizes[0] / 128;
    int blocks = (N + NPB - 1) / NPB;
    size_t smem = 65536;

    cudaFuncSetAttribute(td_mma, cudaFuncAttributeMaxDynamicSharedMemorySize,
                         (int)smem);

    pack_w<<<96, 256>>>(W3_0e, W3_1o, W3_1e, W3_2e);
    td_mma<<<blocks, THREADS, smem>>>(x, W1_0, W1_1, W2_0, W2_1,
                                      (float*)d_out, N);
}